// round 1
// baseline (speedup 1.0000x reference)
#include <cuda_runtime.h>
#include <math.h>

// Problem constants
#define NB 16
#define NN 8192
#define NC 256
#define NH 4
#define ND 64
#define NK 64
#define NCHUNK 8
#define CHUNK 1024   // NN / NCHUNK

// Scratch (no allocations allowed -> __device__ globals)
static __device__ float g_part[NCHUNK * NB * NC * NK];   // 8 MB partial sums
static __device__ float g_skp[NB * NC * NK];             // skip_kp[b][c=h*64+d][k]
static __device__ float g_gvp[NB * NH * ND * NK];        // global_vp[b][h][d1][m]

// ---------------------------------------------------------------------------
// Kernel 0: global_vp[b,h,d1,m] = sum_n1 global_fea[b,n1,h*64+d1] * EF1[n1,m]
// ---------------------------------------------------------------------------
__global__ void k_gvp(const float* __restrict__ gf, const float* __restrict__ ef1) {
    int bh = blockIdx.x, b = bh >> 2, h = bh & 3;
    __shared__ float gs[64][64];   // [n1][d1]
    __shared__ float es[64][64];   // [n1][m]
    int t = threadIdx.x;           // 256 threads
    for (int i = t; i < 4096; i += 256) {
        int r = i >> 6, c = i & 63;
        gs[r][c] = gf[(b * 64 + r) * 256 + h * 64 + c];
        es[r][c] = ef1[i];
    }
    __syncthreads();
    int d0 = (t >> 4) << 2, m0 = (t & 15) << 2;
    float acc[4][4] = {};
    for (int n1 = 0; n1 < 64; n1++) {
        float4 a = *(const float4*)&gs[n1][d0];
        float4 v = *(const float4*)&es[n1][m0];
        float av[4] = {a.x, a.y, a.z, a.w};
        float bv[4] = {v.x, v.y, v.z, v.w};
        #pragma unroll
        for (int i = 0; i < 4; i++)
            #pragma unroll
            for (int j = 0; j < 4; j++)
                acc[i][j] += av[i] * bv[j];
    }
    float* o = g_gvp + (size_t)bh * 4096;
    #pragma unroll
    for (int i = 0; i < 4; i++)
        #pragma unroll
        for (int j = 0; j < 4; j++)
            o[(d0 + i) * 64 + m0 + j] = acc[i][j];
}

// ---------------------------------------------------------------------------
// Kernel 1: partial skip_kp over an N-chunk (deterministic, no atomics)
// part[chunk][b][c][k] = sum_{n in chunk} skip[b,n,c] * EF2[n,k]
// ---------------------------------------------------------------------------
__global__ void k_skp_part(const float* __restrict__ skip, const float* __restrict__ ef2) {
    int chunk = blockIdx.x;   // 0..7
    int ct    = blockIdx.y;   // 0..3, c-tile of 64
    int b     = blockIdx.z;   // 0..15
    __shared__ float ss[8][64];
    __shared__ float es[8][64];
    int t = threadIdx.x;      // 256
    int c0 = (t >> 4) << 2, k0 = (t & 15) << 2;
    float acc[4][4] = {};
    int nbase = chunk * CHUNK;

    for (int n0 = 0; n0 < CHUNK; n0 += 8) {
        __syncthreads();
        {
            int which = t >> 7;         // 0: skip, 1: ef2
            int r = (t >> 4) & 7;       // row within 8-batch
            int c4 = t & 15;            // which float4
            int n = nbase + n0 + r;
            if (which == 0)
                *(float4*)&ss[r][c4 * 4] =
                    *(const float4*)&skip[((size_t)b * NN + n) * NC + ct * 64 + c4 * 4];
            else
                *(float4*)&es[r][c4 * 4] = *(const float4*)&ef2[(size_t)n * 64 + c4 * 4];
        }
        __syncthreads();
        #pragma unroll
        for (int i = 0; i < 8; i++) {
            float4 a = *(const float4*)&ss[i][c0];
            float4 v = *(const float4*)&es[i][k0];
            float av[4] = {a.x, a.y, a.z, a.w};
            float bv[4] = {v.x, v.y, v.z, v.w};
            #pragma unroll
            for (int ii = 0; ii < 4; ii++)
                #pragma unroll
                for (int jj = 0; jj < 4; jj++)
                    acc[ii][jj] += av[ii] * bv[jj];
        }
    }
    float* p = g_part + (((size_t)chunk * NB + b) * NC + ct * 64) * NK;
    #pragma unroll
    for (int i = 0; i < 4; i++)
        #pragma unroll
        for (int j = 0; j < 4; j++)
            p[(c0 + i) * NK + k0 + j] = acc[i][j];
}

// ---------------------------------------------------------------------------
// Kernel 2: reduce partials (fixed order -> deterministic)
// ---------------------------------------------------------------------------
__global__ void k_skp_reduce() {
    int i = blockIdx.x * 256 + threadIdx.x;   // over NB*NC*NK = 262144
    float s = 0.f;
    #pragma unroll
    for (int c = 0; c < NCHUNK; c++) s += g_part[(size_t)c * (NB * NC * NK) + i];
    g_skp[i] = s;
}

// ---------------------------------------------------------------------------
// Kernel 3: fused logits -> softmax -> value matvec -> permuted write
// One thread per (b,h,n) row. skip_kp and global_vp tiles in smem
// (broadcast LDS.128: 1 LDS per 4 FMA). q row + 64 logits in registers.
// ---------------------------------------------------------------------------
__global__ void __launch_bounds__(128) k_attn(
    const float* __restrict__ outq, const float* __restrict__ temp,
    float* __restrict__ x)
{
    int nt = blockIdx.x;   // 0..63 (tile of 128 n)
    int h  = blockIdx.y;
    int b  = blockIdx.z;
    __shared__ float skps[64][64];  // [d][k]
    __shared__ float vps[64][64];   // [k][m]
    int t = threadIdx.x;            // 128

    const float* skp_bh = g_skp + ((size_t)b * NC + h * 64) * NK;
    const float* gvp_bh = g_gvp + (size_t)(b * NH + h) * 4096;
    for (int i = t; i < 4096; i += 128) {
        ((float*)skps)[i] = skp_bh[i];
        ((float*)vps)[i]  = gvp_bh[i];
    }
    __syncthreads();

    float tmp = temp[h];
    int n = nt * 128 + t;
    const float* qrow = outq + ((size_t)b * NN + n) * NC + h * 64;

    float lg[64];
    #pragma unroll
    for (int k = 0; k < 64; k++) lg[k] = 0.f;

    for (int d0 = 0; d0 < 64; d0 += 16) {
        float q[16];
        #pragma unroll
        for (int i = 0; i < 16; i += 4) {
            float4 qq = *(const float4*)&qrow[d0 + i];
            q[i] = qq.x; q[i + 1] = qq.y; q[i + 2] = qq.z; q[i + 3] = qq.w;
        }
        #pragma unroll
        for (int k = 0; k < 64; k += 4) {
            float a0 = lg[k], a1 = lg[k + 1], a2 = lg[k + 2], a3 = lg[k + 3];
            #pragma unroll
            for (int dd = 0; dd < 16; dd++) {
                float4 s = *(const float4*)&skps[d0 + dd][k];
                a0 += q[dd] * s.x;
                a1 += q[dd] * s.y;
                a2 += q[dd] * s.z;
                a3 += q[dd] * s.w;
            }
            lg[k] = a0; lg[k + 1] = a1; lg[k + 2] = a2; lg[k + 3] = a3;
        }
    }

    // temperature + softmax (max-subtracted, matches reference semantics)
    #pragma unroll
    for (int k = 0; k < 64; k++) lg[k] *= tmp;
    float mx = lg[0];
    #pragma unroll
    for (int k = 1; k < 64; k++) mx = fmaxf(mx, lg[k]);
    float sum = 0.f;
    #pragma unroll
    for (int k = 0; k < 64; k++) { lg[k] = __expf(lg[k] - mx); sum += lg[k]; }
    float inv = 1.f / sum;

    // x[b,h,n,m] -> out[b*N*C + m*(H*N) + h*N + n]  (coalesced over n = lane)
    float* od = x + (size_t)b * (NN * NC) + (size_t)h * NN + n;
    for (int m0 = 0; m0 < 64; m0 += 4) {
        float a0 = 0.f, a1 = 0.f, a2 = 0.f, a3 = 0.f;
        #pragma unroll
        for (int k = 0; k < 64; k++) {
            float4 v = *(const float4*)&vps[k][m0];
            a0 += lg[k] * v.x;
            a1 += lg[k] * v.y;
            a2 += lg[k] * v.z;
            a3 += lg[k] * v.w;
        }
        od[(size_t)(m0 + 0) * (NH * NN)] = a0 * inv;
        od[(size_t)(m0 + 1) * (NH * NN)] = a1 * inv;
        od[(size_t)(m0 + 2) * (NH * NN)] = a2 * inv;
        od[(size_t)(m0 + 3) * (NH * NN)] = a3 * inv;
    }
}

// ---------------------------------------------------------------------------
extern "C" void kernel_launch(void* const* d_in, const int* in_sizes, int n_in,
                              void* d_out, int out_size) {
    const float* skip = (const float*)d_in[0];   // (16, 8192, 256)
    const float* outq = (const float*)d_in[1];   // (16, 8192, 256)
    const float* gf   = (const float*)d_in[2];   // (16, 64, 256)
    const float* ef1  = (const float*)d_in[3];   // (64, 64)
    const float* ef2  = (const float*)d_in[4];   // (8192, 64)
    const float* temp = (const float*)d_in[5];   // (4, 1, 1)
    float* x = (float*)d_out;                    // (16, 8192, 256)

    k_gvp<<<NB * NH, 256>>>(gf, ef1);
    k_skp_part<<<dim3(NCHUNK, 4, NB), 256>>>(skip, ef2);
    k_skp_reduce<<<(NB * NC * NK) / 256, 256>>>();
    k_attn<<<dim3(NN / 128, NH, NB), 128>>>(outq, temp, x);
}

// round 2
// speedup vs baseline: 1.3407x; 1.3407x over previous
#include <cuda_runtime.h>
#include <cuda_bf16.h>
#include <mma.h>
#include <math.h>

using namespace nvcuda;

// Problem constants
#define NB 16
#define NN 8192
#define NC 256
#define NH 4
#define NK 64
#define NCHUNK 8

// Scratch (__device__ globals; no allocations allowed)
static __device__ float g_part[NCHUNK * NB * NC * NK];          // 8 MB partials
static __device__ float g_gvp[NB * NH * 64 * 64];               // fp32 global_vp
static __device__ __nv_bfloat16 g_ef2h[NN * NK], g_ef2l[NN * NK];
static __device__ __nv_bfloat16 g_skph[NB * NC * NK], g_skpl[NB * NC * NK];
static __device__ __nv_bfloat16 g_vph[NB * NH * 64 * 64], g_vpl[NB * NH * 64 * 64];

__device__ __forceinline__ void split2(float v, __nv_bfloat16& hi, __nv_bfloat16& lo) {
    hi = __float2bfloat16_rn(v);
    lo = __float2bfloat16_rn(v - __bfloat162float(hi));
}

// ---------------------------------------------------------------------------
// Prep: split EF2 into bf16 hi/lo
// ---------------------------------------------------------------------------
__global__ void k_prep_ef2(const float* __restrict__ ef2) {
    int i = blockIdx.x * 256 + threadIdx.x;          // 524288
    split2(ef2[i], g_ef2h[i], g_ef2l[i]);
}

// ---------------------------------------------------------------------------
// global_vp (fp32, tiny): g_gvp[b,h,d1,m] = sum_n1 gf[b,n1,h*64+d1]*EF1[n1,m]
// ---------------------------------------------------------------------------
__global__ void k_gvp(const float* __restrict__ gf, const float* __restrict__ ef1) {
    int bh = blockIdx.x, b = bh >> 2, h = bh & 3;
    __shared__ float gs[64][64];
    __shared__ float es[64][64];
    int t = threadIdx.x;
    for (int i = t; i < 4096; i += 256) {
        int r = i >> 6, c = i & 63;
        gs[r][c] = gf[(b * 64 + r) * 256 + h * 64 + c];
        es[r][c] = ef1[i];
    }
    __syncthreads();
    int d0 = (t >> 4) << 2, m0 = (t & 15) << 2;
    float acc[4][4] = {};
    for (int n1 = 0; n1 < 64; n1++) {
        float4 a = *(const float4*)&gs[n1][d0];
        float4 v = *(const float4*)&es[n1][m0];
        float av[4] = {a.x, a.y, a.z, a.w};
        float bv[4] = {v.x, v.y, v.z, v.w};
        #pragma unroll
        for (int i = 0; i < 4; i++)
            #pragma unroll
            for (int j = 0; j < 4; j++)
                acc[i][j] += av[i] * bv[j];
    }
    float* o = g_gvp + (size_t)bh * 4096;
    #pragma unroll
    for (int i = 0; i < 4; i++)
        #pragma unroll
        for (int j = 0; j < 4; j++)
            o[(d0 + i) * 64 + m0 + j] = acc[i][j];
}

__global__ void k_prep_vp() {
    int i = blockIdx.x * 256 + threadIdx.x;          // 262144
    split2(g_gvp[i], g_vph[i], g_vpl[i]);
}

// ---------------------------------------------------------------------------
// skip_kp partials via wmma bf16x3:
// part[chunk][b][c][k] = sum_{n in chunk} skip[b,n,c]*EF2[n,k]
// Block: one (chunk, c-tile of 64, b). 8 warps; warp -> 16c x 32k.
// ---------------------------------------------------------------------------
__global__ void __launch_bounds__(256) k_skp(const float* __restrict__ skip) {
    int chunk = blockIdx.x, ct = blockIdx.y, b = blockIdx.z;
    __shared__ __nv_bfloat16 ash[16][72], asl[16][72];   // [n][c] (A^T storage)
    __shared__ __nv_bfloat16 bsh[16][72], bsl[16][72];   // [n][k]
    int t = threadIdx.x, w = t >> 5;

    wmma::fragment<wmma::accumulator, 16, 16, 16, float> acc[2];
    wmma::fill_fragment(acc[0], 0.f);
    wmma::fill_fragment(acc[1], 0.f);
    int c0 = (w >> 1) * 16;
    int kc = (w & 1) * 32;

    // loader indices
    int lr = t >> 4, lc4 = (t & 15) * 4;                 // skip: 16x64 fp32
    int er = (t & 127) >> 3, ek8 = (t & 7) * 8;          // ef2: 16x64 bf16 (hi or lo)

    for (int ns = 0; ns < 64; ns++) {
        int n0 = chunk * 1024 + ns * 16;
        float4 v = *(const float4*)&skip[((size_t)b * NN + n0 + lr) * NC + ct * 64 + lc4];
        if (t < 128)
            *(uint4*)&bsh[er][ek8] = *(const uint4*)&g_ef2h[(size_t)(n0 + er) * 64 + ek8];
        else
            *(uint4*)&bsl[er][ek8] = *(const uint4*)&g_ef2l[(size_t)(n0 + er) * 64 + ek8];
        split2(v.x, ash[lr][lc4 + 0], asl[lr][lc4 + 0]);
        split2(v.y, ash[lr][lc4 + 1], asl[lr][lc4 + 1]);
        split2(v.z, ash[lr][lc4 + 2], asl[lr][lc4 + 2]);
        split2(v.w, ash[lr][lc4 + 3], asl[lr][lc4 + 3]);
        __syncthreads();

        wmma::fragment<wmma::matrix_a, 16, 16, 16, __nv_bfloat16, wmma::col_major> ah, al;
        wmma::load_matrix_sync(ah, &ash[0][c0], 72);
        wmma::load_matrix_sync(al, &asl[0][c0], 72);
        #pragma unroll
        for (int kt = 0; kt < 2; kt++) {
            wmma::fragment<wmma::matrix_b, 16, 16, 16, __nv_bfloat16, wmma::row_major> bh, bl;
            wmma::load_matrix_sync(bh, &bsh[0][kc + kt * 16], 72);
            wmma::load_matrix_sync(bl, &bsl[0][kc + kt * 16], 72);
            wmma::mma_sync(acc[kt], ah, bh, acc[kt]);
            wmma::mma_sync(acc[kt], ah, bl, acc[kt]);
            wmma::mma_sync(acc[kt], al, bh, acc[kt]);
        }
        __syncthreads();
    }
    float* p = g_part + (((size_t)chunk * NB + b) * NC + ct * 64 + c0) * 64 + kc;
    wmma::store_matrix_sync(p, acc[0], 64, wmma::mem_row_major);
    wmma::store_matrix_sync(p + 16, acc[1], 64, wmma::mem_row_major);
}

// ---------------------------------------------------------------------------
// Reduce partials (fixed order) and split skp into bf16 hi/lo
// ---------------------------------------------------------------------------
__global__ void k_reduce() {
    int i = blockIdx.x * 256 + threadIdx.x;              // 262144
    float s = 0.f;
    #pragma unroll
    for (int c = 0; c < NCHUNK; c++) s += g_part[(size_t)c * (NB * NC * NK) + i];
    split2(s, g_skph[i], g_skpl[i]);
}

// ---------------------------------------------------------------------------
// Fused attention via wmma bf16x3:
// logits(128n x 64k) -> softmax -> values(128n x 64m) -> permuted write
// Block: 256 threads (8 warps), one (b, h, n-tile of 128).
// ---------------------------------------------------------------------------
__global__ void __launch_bounds__(256) k_attn(
    const float* __restrict__ outq, const float* __restrict__ temp,
    float* __restrict__ x)
{
    extern __shared__ char smbuf[];
    __nv_bfloat16* qh  = (__nv_bfloat16*)smbuf;          // 128x72 (later probs hi)
    __nv_bfloat16* ql  = qh + 128 * 72;                  // 128x72 (later probs lo)
    __nv_bfloat16* sph = ql + 128 * 72;                  // 64x72
    __nv_bfloat16* spl = sph + 64 * 72;
    __nv_bfloat16* vph = spl + 64 * 72;
    __nv_bfloat16* vpl = vph + 64 * 72;
    float* lg = (float*)(vpl + 64 * 72);                 // 128x72 (logits, later out)

    int nt = blockIdx.x, h = blockIdx.y, b = blockIdx.z;
    int t = threadIdx.x, w = t >> 5;

    // Load small matrices into smem
    {
        size_t skb = ((size_t)b * NC + h * 64) * 64;
        size_t vpb = (size_t)(b * NH + h) * 4096;
        for (int i = t; i < 512; i += 256) {
            int r = i >> 3, k8 = (i & 7) * 8;
            *(uint4*)&sph[r * 72 + k8] = *(const uint4*)&g_skph[skb + r * 64 + k8];
            *(uint4*)&spl[r * 72 + k8] = *(const uint4*)&g_skpl[skb + r * 64 + k8];
            *(uint4*)&vph[r * 72 + k8] = *(const uint4*)&g_vph[vpb + r * 64 + k8];
            *(uint4*)&vpl[r * 72 + k8] = *(const uint4*)&g_vpl[vpb + r * 64 + k8];
        }
    }
    // Load + split q rows
    {
        int r = t >> 1, c0 = (t & 1) * 32;
        const float* qrow = outq + ((size_t)b * NN + nt * 128 + r) * NC + h * 64 + c0;
        #pragma unroll
        for (int j = 0; j < 8; j++) {
            float4 v = *(const float4*)&qrow[j * 4];
            int cc = c0 + j * 4;
            split2(v.x, qh[r * 72 + cc + 0], ql[r * 72 + cc + 0]);
            split2(v.y, qh[r * 72 + cc + 1], ql[r * 72 + cc + 1]);
            split2(v.z, qh[r * 72 + cc + 2], ql[r * 72 + cc + 2]);
            split2(v.w, qh[r * 72 + cc + 3], ql[r * 72 + cc + 3]);
        }
    }
    __syncthreads();

    int r0 = w * 16;
    // Logits GEMM: [16n x 64d] @ [64d x 64k]
    {
        wmma::fragment<wmma::accumulator, 16, 16, 16, float> acc[4];
        #pragma unroll
        for (int kt = 0; kt < 4; kt++) wmma::fill_fragment(acc[kt], 0.f);
        #pragma unroll
        for (int dt = 0; dt < 4; dt++) {
            wmma::fragment<wmma::matrix_a, 16, 16, 16, __nv_bfloat16, wmma::row_major> ah, al;
            wmma::load_matrix_sync(ah, &qh[r0 * 72 + dt * 16], 72);
            wmma::load_matrix_sync(al, &ql[r0 * 72 + dt * 16], 72);
            #pragma unroll
            for (int kt = 0; kt < 4; kt++) {
                wmma::fragment<wmma::matrix_b, 16, 16, 16, __nv_bfloat16, wmma::row_major> bh, bl;
                wmma::load_matrix_sync(bh, &sph[dt * 16 * 72 + kt * 16], 72);
                wmma::load_matrix_sync(bl, &spl[dt * 16 * 72 + kt * 16], 72);
                wmma::mma_sync(acc[kt], ah, bh, acc[kt]);
                wmma::mma_sync(acc[kt], ah, bl, acc[kt]);
                wmma::mma_sync(acc[kt], al, bh, acc[kt]);
            }
        }
        #pragma unroll
        for (int kt = 0; kt < 4; kt++)
            wmma::store_matrix_sync(&lg[r0 * 72 + kt * 16], acc[kt], 72, wmma::mem_row_major);
    }
    __syncthreads();

    // Softmax per row (threads 0..127), write normalized probs as bf16 hi/lo
    if (t < 128) {
        float tempv = temp[h];
        float* row = lg + t * 72;
        float mx = -1e30f;
        #pragma unroll
        for (int k = 0; k < 64; k++) mx = fmaxf(mx, row[k] * tempv);
        float sum = 0.f;
        #pragma unroll
        for (int k = 0; k < 64; k++) {
            float e = __expf(row[k] * tempv - mx);
            row[k] = e;
            sum += e;
        }
        float inv = 1.f / sum;
        #pragma unroll
        for (int k = 0; k < 64; k++)
            split2(row[k] * inv, qh[t * 72 + k], ql[t * 72 + k]);
    }
    __syncthreads();

    // Values GEMM: probs[16n x 64k] @ vp[64k x 64m]
    {
        wmma::fragment<wmma::accumulator, 16, 16, 16, float> acc2[4];
        #pragma unroll
        for (int mt = 0; mt < 4; mt++) wmma::fill_fragment(acc2[mt], 0.f);
        #pragma unroll
        for (int kt = 0; kt < 4; kt++) {
            wmma::fragment<wmma::matrix_a, 16, 16, 16, __nv_bfloat16, wmma::row_major> ah, al;
            wmma::load_matrix_sync(ah, &qh[r0 * 72 + kt * 16], 72);
            wmma::load_matrix_sync(al, &ql[r0 * 72 + kt * 16], 72);
            #pragma unroll
            for (int mt = 0; mt < 4; mt++) {
                wmma::fragment<wmma::matrix_b, 16, 16, 16, __nv_bfloat16, wmma::row_major> bh, bl;
                wmma::load_matrix_sync(bh, &vph[kt * 16 * 72 + mt * 16], 72);
                wmma::load_matrix_sync(bl, &vpl[kt * 16 * 72 + mt * 16], 72);
                wmma::mma_sync(acc2[mt], ah, bh, acc2[mt]);
                wmma::mma_sync(acc2[mt], ah, bl, acc2[mt]);
                wmma::mma_sync(acc2[mt], al, bh, acc2[mt]);
            }
        }
        __syncthreads();   // lg (logit buffer) reuse for output
        #pragma unroll
        for (int mt = 0; mt < 4; mt++)
            wmma::store_matrix_sync(&lg[r0 * 72 + mt * 16], acc2[mt], 72, wmma::mem_row_major);
    }
    __syncthreads();

    // Permuted writeback: x[b, m*(H*N) + h*N + n], coalesced over n
    {
        int m = t >> 2, rq = (t & 3) * 32;
        float* od = x + (size_t)b * (NN * NC) + (size_t)m * (NH * NN) + (size_t)h * NN + nt * 128;
        #pragma unroll
        for (int r = rq; r < rq + 32; r += 4) {
            float4 o;
            o.x = lg[(r + 0) * 72 + m];
            o.y = lg[(r + 1) * 72 + m];
            o.z = lg[(r + 2) * 72 + m];
            o.w = lg[(r + 3) * 72 + m];
            *(float4*)&od[r] = o;
        }
    }
}

// ---------------------------------------------------------------------------
extern "C" void kernel_launch(void* const* d_in, const int* in_sizes, int n_in,
                              void* d_out, int out_size) {
    const float* skip = (const float*)d_in[0];   // (16, 8192, 256)
    const float* outq = (const float*)d_in[1];   // (16, 8192, 256)
    const float* gf   = (const float*)d_in[2];   // (16, 64, 256)
    const float* ef1  = (const float*)d_in[3];   // (64, 64)
    const float* ef2  = (const float*)d_in[4];   // (8192, 64)
    const float* temp = (const float*)d_in[5];   // (4, 1, 1)
    float* x = (float*)d_out;                    // (16, 8192, 256)

    static bool attr_set = false;
    if (!attr_set) {
        cudaFuncSetAttribute(k_attn, cudaFuncAttributeMaxDynamicSharedMemorySize, 110592);
        attr_set = true;
    }

    k_prep_ef2<<<(NN * NK) / 256, 256>>>(ef2);
    k_gvp<<<NB * NH, 256>>>(gf, ef1);
    k_prep_vp<<<(NB * NH * 64 * 64) / 256, 256>>>();
    k_skp<<<dim3(NCHUNK, 4, NB), 256>>>(skip);
    k_reduce<<<(NB * NC * NK) / 256, 256>>>();
    k_attn<<<dim3(NN / 128, NH, NB), 256, 110592>>>(outq, temp, x);
}